// round 15
// baseline (speedup 1.0000x reference)
#include <cuda_runtime.h>
#include <math.h>
#include <cstdint>

// Problem constants
#define Bv 2
#define Sv 2048
#define Ev 1024
#define Hv 16
#define Dv 64
#define N3 3072
#define BHv 32
#define KDIM 1024

// ---------------- device scratch (static, allocation-free) ----------------
__device__ float g_HR[Bv*Sv*Ev];           // tf32-rounded hidden
__device__ float g_Q[Bv*Hv*Sv*Dv];
__device__ float g_K[Bv*Hv*Sv*Dv];
__device__ float g_V[Bv*Hv*Sv*Dv];
__device__ float g_AO[Bv*Sv*Ev];
__device__ float g_WAT[(size_t)N3*Ev];     // w_attn^T (tf32-rounded)
__device__ float g_WPT[(size_t)Ev*Ev];     // w_proj^T (tf32-rounded)
__device__ float g_part[(size_t)BHv*16*Sv];// per-(bh, coltile, row) partial sum(exp)
__device__ float g_Wscratch[(size_t)Bv*Hv*Sv*Sv];

// ==================== helpers ====================
__device__ __forceinline__ uint32_t smem_u32(const void* p) {
    uint32_t a;
    asm("{ .reg .u64 t; cvta.to.shared.u64 t, %1; cvt.u32.u64 %0, t; }"
        : "=r"(a) : "l"(p));
    return a;
}
__device__ __forceinline__ uint32_t cvt_tf32(float f) {
    uint32_t o;
    asm("cvt.rna.tf32.f32 %0, %1;" : "=r"(o) : "f"(f));
    return o;
}
__device__ __forceinline__ float tf32f(float f) {
    return __uint_as_float(cvt_tf32(f));
}
#define CP16(dst, src) \
    asm volatile("cp.async.cg.shared.global [%0], [%1], 16;" \
                 :: "r"(dst), "l"(src) : "memory")
#define CP_COMMIT() asm volatile("cp.async.commit_group;" ::: "memory")
#define CP_WAIT1()  asm volatile("cp.async.wait_group 1;" ::: "memory")
#define CP_WAIT0()  asm volatile("cp.async.wait_group 0;" ::: "memory")

#define MMA_TF32(d, a, b) \
    asm volatile("mma.sync.aligned.m16n8k8.row.col.f32.tf32.tf32.f32 " \
        "{%0,%1,%2,%3}, {%4,%5,%6,%7}, {%8,%9}, {%0,%1,%2,%3};" \
        : "+f"((d).x), "+f"((d).y), "+f"((d).z), "+f"((d).w) \
        : "r"((a)[0]), "r"((a)[1]), "r"((a)[2]), "r"((a)[3]), \
          "r"((b)[0]), "r"((b)[1]))

// ============================================================
// Zero-fill helper (R11/R13-measured): each qkv block clears 5 whole
// 128x128 strictly-upper tiles of attn_weights (streaming stores).
// ============================================================
__device__ __forceinline__ void zero_upper_chunk(float* __restrict__ wts, int id) {
    int tid = threadIdx.x;
    int trow = tid >> 5;
    int tcol = tid & 31;
    const float4 z = make_float4(0.f, 0.f, 0.f, 0.f);
#pragma unroll
    for (int tt = 0; tt < 5; tt++) {
        int tile = id * 5 + tt;
        int bh = tile / 120;
        int t = tile - bh * 120;
        int u = 119 - t;
        int m = (int)((sqrtf((float)(8 * u + 1)) - 1.0f) * 0.5f);
        while ((m + 1) * (m + 2) / 2 <= u) m++;
        while (m * (m + 1) / 2 > u) m--;
        int ry = 14 - m;
        int pref = 15 * ry - (ry * (ry - 1)) / 2;
        int cx = ry + 1 + (t - pref);
        float4* p = (float4*)(wts + ((size_t)bh * Sv + ry * 128 + trow) * Sv
                                  + cx * 128 + tcol * 4);
#pragma unroll
        for (int j = 0; j < 16; j++) {
            __stcs(p, z);
            p += 2 * Sv;
        }
    }
}

// ============================================================
// Pre-pass: round a float array to tf32 (rna) into dst.
// ============================================================
__global__ void __launch_bounds__(256) round_tf32_kernel(const float* __restrict__ src,
                                                         float* __restrict__ dst) {
    int i = blockIdx.x * 256 + threadIdx.x;
    float4 v = ((const float4*)src)[i];
    v.x = tf32f(v.x); v.y = tf32f(v.y); v.z = tf32f(v.z); v.w = tf32f(v.w);
    ((float4*)dst)[i] = v;
}

// ============================================================
// Transpose + tf32 rounding: src[R][C] -> dst[C][R]
// ============================================================
__global__ void transpose_k(const float* __restrict__ src, float* __restrict__ dst,
                            int R, int C) {
    __shared__ float t[32][33];
    int bx = blockIdx.x * 32, by = blockIdx.y * 32;
    int x = bx + threadIdx.x;
#pragma unroll
    for (int i = threadIdx.y; i < 32; i += 8)
        t[i][threadIdx.x] = src[(size_t)(by + i) * C + x];
    __syncthreads();
    int x2 = by + threadIdx.x;
#pragma unroll
    for (int i = threadIdx.y; i < 32; i += 8)
        dst[(size_t)(bx + i) * R + x2] = tf32f(t[threadIdx.x][i]);
}

// ============================================================
// Shared GEMM mainloop: 128x128 tile, K=1024, BK=32, 8 warps.
// ============================================================
__device__ __forceinline__ void gemm_loop_1024(const float* __restrict__ Ag,
                                               const float* __restrict__ Bg,
                                               float* sm, float4 acc[4][4]) {
    int tid = threadIdx.x, lane = tid & 31, wid = tid >> 5;
    int wm = wid >> 2, wn = wid & 3;
    int lr = lane >> 2, lc = lane & 3;

    const int PITCH = 36;
    const int ABUF = 128 * PITCH;
    float* As = sm;
    float* Bs = sm + 2 * ABUF;

#pragma unroll
    for (int i = 0; i < 4; i++)
#pragma unroll
        for (int j = 0; j < 4; j++) acc[i][j] = make_float4(0.f, 0.f, 0.f, 0.f);

#pragma unroll
    for (int it = 0; it < 4; it++) {
        int idx = tid + it * 256;
        int row = idx >> 3, c4 = idx & 7;
        CP16(smem_u32(As + row * PITCH + c4 * 4), Ag + (size_t)row * KDIM + c4 * 4);
        CP16(smem_u32(Bs + row * PITCH + c4 * 4), Bg + (size_t)row * KDIM + c4 * 4);
    }
    CP_COMMIT();

    const int NIT = KDIM / 32;
    for (int it = 0; it < NIT; it++) {
        int buf = it & 1;
        if (it + 1 < NIT) {
            int k0 = (it + 1) * 32;
            int nb = buf ^ 1;
#pragma unroll
            for (int l = 0; l < 4; l++) {
                int idx = tid + l * 256;
                int row = idx >> 3, c4 = idx & 7;
                CP16(smem_u32(As + nb * ABUF + row * PITCH + c4 * 4),
                     Ag + (size_t)row * KDIM + k0 + c4 * 4);
                CP16(smem_u32(Bs + nb * ABUF + row * PITCH + c4 * 4),
                     Bg + (size_t)row * KDIM + k0 + c4 * 4);
            }
            CP_COMMIT();
            CP_WAIT1();
        } else {
            CP_WAIT0();
        }
        __syncthreads();

        const float* Ab = As + buf * ABUF;
        const float* Bb = Bs + buf * ABUF;
#pragma unroll
        for (int kk = 0; kk < 32; kk += 8) {
            uint32_t af[4][4];
#pragma unroll
            for (int mt = 0; mt < 4; mt++) {
                int row = wm * 64 + mt * 16 + lr;
                af[mt][0] = __float_as_uint(Ab[row * PITCH + kk + lc]);
                af[mt][1] = __float_as_uint(Ab[(row + 8) * PITCH + kk + lc]);
                af[mt][2] = __float_as_uint(Ab[row * PITCH + kk + lc + 4]);
                af[mt][3] = __float_as_uint(Ab[(row + 8) * PITCH + kk + lc + 4]);
            }
            uint32_t bf[4][2];
#pragma unroll
            for (int nt = 0; nt < 4; nt++) {
                int n = wn * 32 + nt * 8 + lr;
                bf[nt][0] = __float_as_uint(Bb[n * PITCH + kk + lc]);
                bf[nt][1] = __float_as_uint(Bb[n * PITCH + kk + lc + 4]);
            }
#pragma unroll
            for (int mt = 0; mt < 4; mt++)
#pragma unroll
                for (int nt = 0; nt < 4; nt++)
                    MMA_TF32(acc[mt][nt], af[mt], bf[nt]);
        }
        __syncthreads();
    }
}

// ============================================================
// Kernel 1: QKV GEMM (mma tf32) + upper-triangle zero-fill after
// the prologue prefetch (overlaps its DRAM latency). R13-measured.
// ============================================================
__global__ void __launch_bounds__(256) qkv_gemm_mma(const float* __restrict__ bias,
                                                    float* __restrict__ wts) {
    extern __shared__ float sm[];
    int m0 = blockIdx.y * 128, n0 = blockIdx.x * 128;
    int tid = threadIdx.x, lane = tid & 31, wid = tid >> 5;
    int wm = wid >> 2, wn = wid & 3;
    int lr = lane >> 2, lc = lane & 3;

    const float* Ag = g_HR + (size_t)m0 * KDIM;
    const float* Bg = g_WAT + (size_t)n0 * KDIM;

    const int PITCH = 36;
    const int ABUF = 128 * PITCH;
    float* As = sm;
    float* Bs = sm + 2 * ABUF;

    float4 acc[4][4];
#pragma unroll
    for (int i = 0; i < 4; i++)
#pragma unroll
        for (int j = 0; j < 4; j++) acc[i][j] = make_float4(0.f, 0.f, 0.f, 0.f);

#pragma unroll
    for (int it = 0; it < 4; it++) {
        int idx = tid + it * 256;
        int row = idx >> 3, c4 = idx & 7;
        CP16(smem_u32(As + row * PITCH + c4 * 4), Ag + (size_t)row * KDIM + c4 * 4);
        CP16(smem_u32(Bs + row * PITCH + c4 * 4), Bg + (size_t)row * KDIM + c4 * 4);
    }
    CP_COMMIT();

    zero_upper_chunk(wts, blockIdx.y * 24 + blockIdx.x);

    const int NIT = KDIM / 32;
    for (int it = 0; it < NIT; it++) {
        int buf = it & 1;
        if (it + 1 < NIT) {
            int k0 = (it + 1) * 32;
            int nb = buf ^ 1;
#pragma unroll
            for (int l = 0; l < 4; l++) {
                int idx = tid + l * 256;
                int row = idx >> 3, c4 = idx & 7;
                CP16(smem_u32(As + nb * ABUF + row * PITCH + c4 * 4),
                     Ag + (size_t)row * KDIM + k0 + c4 * 4);
                CP16(smem_u32(Bs + nb * ABUF + row * PITCH + c4 * 4),
                     Bg + (size_t)row * KDIM + k0 + c4 * 4);
            }
            CP_COMMIT();
            CP_WAIT1();
        } else {
            CP_WAIT0();
        }
        __syncthreads();

        const float* Ab = As + buf * ABUF;
        const float* Bb = Bs + buf * ABUF;
#pragma unroll
        for (int kk = 0; kk < 32; kk += 8) {
            uint32_t af[4][4];
#pragma unroll
            for (int mt = 0; mt < 4; mt++) {
                int row = wm * 64 + mt * 16 + lr;
                af[mt][0] = __float_as_uint(Ab[row * PITCH + kk + lc]);
                af[mt][1] = __float_as_uint(Ab[(row + 8) * PITCH + kk + lc]);
                af[mt][2] = __float_as_uint(Ab[row * PITCH + kk + lc + 4]);
                af[mt][3] = __float_as_uint(Ab[(row + 8) * PITCH + kk + lc + 4]);
            }
            uint32_t bf[4][2];
#pragma unroll
            for (int nt = 0; nt < 4; nt++) {
                int n = wn * 32 + nt * 8 + lr;
                bf[nt][0] = __float_as_uint(Bb[n * PITCH + kk + lc]);
                bf[nt][1] = __float_as_uint(Bb[n * PITCH + kk + lc + 4]);
            }
#pragma unroll
            for (int mt = 0; mt < 4; mt++)
#pragma unroll
                for (int nt = 0; nt < 4; nt++)
                    MMA_TF32(acc[mt][nt], af[mt], bf[nt]);
        }
        __syncthreads();
    }

#pragma unroll
    for (int mt = 0; mt < 4; mt++) {
#pragma unroll
        for (int nt = 0; nt < 4; nt++) {
            int col = n0 + wn * 32 + nt * 8 + lc * 2;
            int which = col >> 10;
            int e = col & 1023;
            int h = e >> 6, d = e & 63;
            float* dstb = (which == 0) ? g_Q : (which == 1) ? g_K : g_V;
            float b0 = bias[col], b1 = bias[col + 1];
#pragma unroll
            for (int half = 0; half < 2; half++) {
                int row = m0 + wm * 64 + mt * 16 + lr + half * 8;
                int b = row >> 11, s = row & 2047;
                float* dp = dstb + (((size_t)b * Hv + h) * Sv + s) * Dv + d;
                float v0 = (half ? acc[mt][nt].z : acc[mt][nt].x) + b0;
                float v1 = (half ? acc[mt][nt].w : acc[mt][nt].y) + b1;
                *(float2*)dp = make_float2(tf32f(v0), tf32f(v1));
            }
        }
    }
}

// ============================================================
// Kernel 4: projection (mma tf32). A = g_AO, B = g_WPT. -> d_out.
// Streaming output stores (write-once, never re-read).
// ============================================================
__global__ void __launch_bounds__(256) proj_gemm_mma(const float* __restrict__ bias,
                                                     float* __restrict__ C) {
    extern __shared__ float sm[];
    int m0 = blockIdx.y * 128, n0 = blockIdx.x * 128;
    float4 acc[4][4];
    gemm_loop_1024(g_AO + (size_t)m0 * KDIM, g_WPT + (size_t)n0 * KDIM, sm, acc);

    int lane = threadIdx.x & 31, wid = threadIdx.x >> 5;
    int wm = wid >> 2, wn = wid & 3;
    int lr = lane >> 2, lc = lane & 3;

#pragma unroll
    for (int mt = 0; mt < 4; mt++) {
#pragma unroll
        for (int nt = 0; nt < 4; nt++) {
            int col = n0 + wn * 32 + nt * 8 + lc * 2;
            float b0 = bias[col], b1 = bias[col + 1];
#pragma unroll
            for (int half = 0; half < 2; half++) {
                int row = m0 + wm * 64 + mt * 16 + lr + half * 8;
                float v0 = (half ? acc[mt][nt].z : acc[mt][nt].x) + b0;
                float v1 = (half ? acc[mt][nt].w : acc[mt][nt].y) + b1;
                __stcs((float2*)(C + (size_t)row * Ev + col), make_float2(v0, v1));
            }
        }
    }
}

// ============================================================
// Kernel 2: scores (mma tf32): e = exp((Q K^T)/8), causal mask -> 0.
// Writes e (STREAMING - e is always evicted before pv reads it, so
// caching it only thrashes L2) on lower/diag tiles; emits partial
// sums to g_part.
// ============================================================
__global__ void __launch_bounds__(256) scores_mma(float* __restrict__ Wout) {
    int bh = blockIdx.z;
    int c0 = blockIdx.x * 128;
    int r0 = blockIdx.y * 128;
    if (c0 > r0) return;   // upper tiles already zero-filled by qkv
    float* out = Wout + (size_t)bh * Sv * Sv;
    int tid = threadIdx.x;

    extern __shared__ float sm[];
    __shared__ float sred[4][128];
    const int PITCH = 68;
    float* Qs = sm;
    float* Ks = sm + 128 * PITCH;

    const float* Q = g_Q + (size_t)bh * Sv * Dv;
    const float* Kp = g_K + (size_t)bh * Sv * Dv;

#pragma unroll
    for (int it = 0; it < 8; it++) {
        int idx = tid + it * 256;
        int row = idx >> 4;
        int c4 = idx & 15;
        CP16(smem_u32(Qs + row * PITCH + c4 * 4), Q + (size_t)(r0 + row) * Dv + c4 * 4);
        CP16(smem_u32(Ks + row * PITCH + c4 * 4), Kp + (size_t)(c0 + row) * Dv + c4 * 4);
    }
    CP_COMMIT();
    CP_WAIT0();
    __syncthreads();

    int lane = tid & 31, wid = tid >> 5;
    int wm = wid >> 2, wn = wid & 3;
    int lr = lane >> 2, lc = lane & 3;

    float4 acc[4][4];
#pragma unroll
    for (int i = 0; i < 4; i++)
#pragma unroll
        for (int j = 0; j < 4; j++) acc[i][j] = make_float4(0.f, 0.f, 0.f, 0.f);

#pragma unroll
    for (int kk = 0; kk < 64; kk += 8) {
        uint32_t af[4][4];
#pragma unroll
        for (int mt = 0; mt < 4; mt++) {
            int row = wm * 64 + mt * 16 + lr;
            af[mt][0] = __float_as_uint(Qs[row * PITCH + kk + lc]);
            af[mt][1] = __float_as_uint(Qs[(row + 8) * PITCH + kk + lc]);
            af[mt][2] = __float_as_uint(Qs[row * PITCH + kk + lc + 4]);
            af[mt][3] = __float_as_uint(Qs[(row + 8) * PITCH + kk + lc + 4]);
        }
        uint32_t bf[4][2];
#pragma unroll
        for (int nt = 0; nt < 4; nt++) {
            int n = wn * 32 + nt * 8 + lr;
            bf[nt][0] = __float_as_uint(Ks[n * PITCH + kk + lc]);
            bf[nt][1] = __float_as_uint(Ks[n * PITCH + kk + lc + 4]);
        }
#pragma unroll
        for (int mt = 0; mt < 4; mt++)
#pragma unroll
            for (int nt = 0; nt < 4; nt++)
                MMA_TF32(acc[mt][nt], af[mt], bf[nt]);
    }

    const float scale = 0.125f;
#pragma unroll
    for (int mt = 0; mt < 4; mt++) {
#pragma unroll
        for (int half = 0; half < 2; half++) {
            int r = r0 + wm * 64 + mt * 16 + lr + half * 8;
            float rsum = 0.f;
#pragma unroll
            for (int nt = 0; nt < 4; nt++) {
                int col = c0 + wn * 32 + nt * 8 + lc * 2;
                float v0 = (half ? acc[mt][nt].z : acc[mt][nt].x) * scale;
                float v1 = (half ? acc[mt][nt].w : acc[mt][nt].y) * scale;
                float e0 = (col <= r) ? __expf(v0) : 0.f;
                float e1 = (col + 1 <= r) ? __expf(v1) : 0.f;
                __stcs((float2*)(out + (size_t)r * Sv + col), make_float2(e0, e1));
                rsum += e0 + e1;
            }
            rsum += __shfl_xor_sync(0xffffffffu, rsum, 1);
            rsum += __shfl_xor_sync(0xffffffffu, rsum, 2);
            if (lc == 0)
                sred[wn][wm * 64 + mt * 16 + half * 8 + lr] = rsum;
        }
    }
    __syncthreads();
    if (tid < 128) {
        float p = sred[0][tid] + sred[1][tid] + sred[2][tid] + sred[3][tid];
        g_part[((size_t)bh * 16 + (c0 >> 7)) * Sv + r0 + tid] = p;
    }
}

// ============================================================
// Kernel 3: fused normalize + PV (mma tf32), cp.async double-buffered.
// Reads e; computes w = e * rinv in registers, writes final
// attn_weights back to gmem overlapped with the MMA loop, and
// accumulates P@V into g_AO. (R13-measured.)
// ============================================================
__global__ void __launch_bounds__(256) pv_fused2(float* __restrict__ Wts) {
    int bh = blockIdx.y;
    int rt = (gridDim.x - 1) - blockIdx.x;   // heavy row-tiles first
    int r0 = rt * 128;
    float* P = Wts + (size_t)bh * Sv * Sv;
    const float* V = g_V + (size_t)bh * Sv * Dv;

    extern __shared__ float sm[];
    const int PP = 36, VP = 72;
    const int PBUF = 128 * PP;
    const int VBUF = 32 * VP;
    float* Ps = sm;
    float* Vs = sm + 2 * PBUF;
    __shared__ float rinv[128];

    int tid = threadIdx.x, lane = tid & 31, wid = tid >> 5;
    int wm = wid >> 1, wn = wid & 1;
    int lr = lane >> 2, lc = lane & 3;

    if (tid < 128) {
        float s = 0.f;
        const float* pp = g_part + (size_t)bh * 16 * Sv + r0 + tid;
        for (int ct = 0; ct <= rt; ct++) s += pp[(size_t)ct * Sv];
        rinv[tid] = 1.0f / s;
    }

    float4 acc[2][4];
#pragma unroll
    for (int i = 0; i < 2; i++)
#pragma unroll
        for (int j = 0; j < 4; j++) acc[i][j] = make_float4(0.f, 0.f, 0.f, 0.f);

    int kend = r0 + 128;
    int nit = kend >> 5;

    // prologue: stage 0
    {
#pragma unroll
        for (int it = 0; it < 4; it++) {
            int idx = tid + it * 256;
            int row = idx >> 3, c4 = idx & 7;
            CP16(smem_u32(Ps + row * PP + c4 * 4),
                 P + (size_t)(r0 + row) * Sv + c4 * 4);
        }
#pragma unroll
        for (int it = 0; it < 2; it++) {
            int idx = tid + it * 256;
            int row = idx >> 4, c4 = idx & 15;
            CP16(smem_u32(Vs + row * VP + c4 * 4),
                 V + (size_t)row * Dv + c4 * 4);
        }
        CP_COMMIT();
    }

    __syncthreads();
    float ri[2][2];
#pragma unroll
    for (int mt = 0; mt < 2; mt++) {
        ri[mt][0] = rinv[wm * 32 + mt * 16 + lr];
        ri[mt][1] = rinv[wm * 32 + mt * 16 + lr + 8];
    }
    float riw[4];
#pragma unroll
    for (int it = 0; it < 4; it++) riw[it] = rinv[(tid >> 3) + it * 32];

    for (int itk = 0; itk < nit; itk++) {
        int buf = itk & 1;
        int kc = itk * 32;
        if (itk + 1 < nit) {
            int kn = (itk + 1) * 32;
            int nb = buf ^ 1;
#pragma unroll
            for (int it = 0; it < 4; it++) {
                int idx = tid + it * 256;
                int row = idx >> 3, c4 = idx & 7;
                CP16(smem_u32(Ps + nb * PBUF + row * PP + c4 * 4),
                     P + (size_t)(r0 + row) * Sv + kn + c4 * 4);
            }
#pragma unroll
            for (int it = 0; it < 2; it++) {
                int idx = tid + it * 256;
                int row = idx >> 4, c4 = idx & 15;
                CP16(smem_u32(Vs + nb * VBUF + row * VP + c4 * 4),
                     V + (size_t)(kn + row) * Dv + c4 * 4);
            }
            CP_COMMIT();
            CP_WAIT1();
        } else {
            CP_WAIT0();
        }
        __syncthreads();

        const float* Pb = Ps + buf * PBUF;
        const float* Vb = Vs + buf * VBUF;

        // stream final attn_weights w = e * rinv back to gmem (write-once)
#pragma unroll
        for (int it = 0; it < 4; it++) {
            int idx = tid + it * 256;
            int row = idx >> 3, c4 = idx & 7;
            float4 ev = *(const float4*)(Pb + row * PP + c4 * 4);
            float inv = riw[it];
            ev.x *= inv; ev.y *= inv; ev.z *= inv; ev.w *= inv;
            __stcs((float4*)(P + (size_t)(r0 + row) * Sv + kc + c4 * 4), ev);
        }

#pragma unroll
        for (int kk = 0; kk < 32; kk += 8) {
            uint32_t af[2][4];
#pragma unroll
            for (int mt = 0; mt < 2; mt++) {
                int row = wm * 32 + mt * 16 + lr;
                af[mt][0] = cvt_tf32(Pb[row * PP + kk + lc] * ri[mt][0]);
                af[mt][1] = cvt_tf32(Pb[(row + 8) * PP + kk + lc] * ri[mt][1]);
                af[mt][2] = cvt_tf32(Pb[row * PP + kk + lc + 4] * ri[mt][0]);
                af[mt][3] = cvt_tf32(Pb[(row + 8) * PP + kk + lc + 4] * ri[mt][1]);
            }
            uint32_t bf[4][2];
#pragma unroll
            for (int nt = 0; nt < 4; nt++) {
                int n = wn * 32 + nt * 8 + lr;
                bf[nt][0] = __float_as_uint(Vb[(kk + lc) * VP + n]);
                bf[nt][1] = __float_as_uint(Vb[(kk + 4 + lc) * VP + n]);
            }
#pragma unroll
            for (int mt = 0; mt < 2; mt++)
#pragma unroll
                for (int nt = 0; nt < 4; nt++)
                    MMA_TF32(acc[mt][nt], af[mt], bf[nt]);
        }
        __syncthreads();
    }

    int b = bh >> 4, h = bh & 15;
#pragma unroll
    for (int mt = 0; mt < 2; mt++) {
#pragma unroll
        for (int nt = 0; nt < 4; nt++) {
            int d = wn * 32 + nt * 8 + lc * 2;
#pragma unroll
            for (int half = 0; half < 2; half++) {
                int r = r0 + wm * 32 + mt * 16 + lr + half * 8;
                float v0 = half ? acc[mt][nt].z : acc[mt][nt].x;
                float v1 = half ? acc[mt][nt].w : acc[mt][nt].y;
                float* dp = g_AO + ((size_t)(b * Sv + r)) * Ev + h * Dv + d;
                *(float2*)dp = make_float2(tf32f(v0), tf32f(v1));
            }
        }
    }
}

// ============================================================
// Launch
// ============================================================
extern "C" void kernel_launch(void* const* d_in, const int* in_sizes, int n_in,
                              void* d_out, int out_size) {
    const float* hs     = (const float*)d_in[0];
    const float* w_attn = (const float*)d_in[1];
    const float* b_attn = (const float*)d_in[2];
    const float* w_proj = (const float*)d_in[3];
    const float* b_proj = (const float*)d_in[4];
    float* out = (float*)d_out;

    const size_t AO_N = (size_t)Bv * Sv * Ev;
    const size_t W_N  = (size_t)Bv * Hv * Sv * Sv;

    float* wts;
    if ((size_t)out_size >= AO_N + W_N) {
        wts = out + AO_N;
    } else {
        void* p = nullptr;
        cudaGetSymbolAddress(&p, g_Wscratch);
        wts = (float*)p;
    }

    float* hr;  { void* p = nullptr; cudaGetSymbolAddress(&p, g_HR);  hr  = (float*)p; }
    float* wat; { void* p = nullptr; cudaGetSymbolAddress(&p, g_WAT); wat = (float*)p; }
    float* wpt; { void* p = nullptr; cudaGetSymbolAddress(&p, g_WPT); wpt = (float*)p; }

    const int GEMM_SMEM = 2 * 2 * 128 * 36 * 4;            // 73728
    const int SCORES_SMEM = 2 * 128 * 68 * 4;              // 69632
    const int PV_SMEM = (2 * 128 * 36 + 2 * 32 * 72) * 4;  // 55296
    cudaFuncSetAttribute(qkv_gemm_mma,
                         cudaFuncAttributeMaxDynamicSharedMemorySize, GEMM_SMEM);
    cudaFuncSetAttribute(proj_gemm_mma,
                         cudaFuncAttributeMaxDynamicSharedMemorySize, GEMM_SMEM);
    cudaFuncSetAttribute(scores_mma,
                         cudaFuncAttributeMaxDynamicSharedMemorySize, SCORES_SMEM);
    cudaFuncSetAttribute(pv_fused2,
                         cudaFuncAttributeMaxDynamicSharedMemorySize, PV_SMEM);

    round_tf32_kernel<<<(Bv * Sv * Ev) / (256 * 4), 256>>>(hs, hr);
    transpose_k<<<dim3(N3 / 32, Ev / 32), dim3(32, 8)>>>(w_attn, wat, Ev, N3);
    transpose_k<<<dim3(Ev / 32, Ev / 32), dim3(32, 8)>>>(w_proj, wpt, Ev, Ev);

    qkv_gemm_mma<<<dim3(N3 / 128, (Bv * Sv) / 128), 256, GEMM_SMEM>>>(b_attn, wts);
    scores_mma<<<dim3(Sv / 128, Sv / 128, BHv), 256, SCORES_SMEM>>>(wts);
    pv_fused2<<<dim3(Sv / 128, BHv), 256, PV_SMEM>>>(wts);
    proj_gemm_mma<<<dim3(Ev / 128, (Bv * Sv) / 128), 256, GEMM_SMEM>>>(b_proj, out);
}

// round 16
// speedup vs baseline: 1.0863x; 1.0863x over previous
#include <cuda_runtime.h>
#include <math.h>
#include <cstdint>

// Problem constants
#define Bv 2
#define Sv 2048
#define Ev 1024
#define Hv 16
#define Dv 64
#define N3 3072
#define BHv 32
#define KDIM 1024

// ---------------- device scratch (static, allocation-free) ----------------
// NOTE: g_HR, g_WAT, g_WPT, g_AO store the K-dimension PERMUTED within each
// 8-group: orig col c -> (c<4 ? 2c : 2(c-4)+1). This makes mma.sync tf32
// fragment pairs (k, k+4) adjacent in smem -> LDS.64 instead of 2x LDS.32.
__device__ float g_HR[Bv*Sv*Ev];           // tf32-rounded hidden (k-permuted)
__device__ float g_Q[Bv*Hv*Sv*Dv];         // unpermuted
__device__ float g_K[Bv*Hv*Sv*Dv];         // unpermuted
__device__ float g_V[Bv*Hv*Sv*Dv];         // unpermuted
__device__ float g_AO[Bv*Sv*Ev];           // (k-permuted for proj)
__device__ float g_WAT[(size_t)N3*Ev];     // w_attn^T (tf32, k-permuted)
__device__ float g_WPT[(size_t)Ev*Ev];     // w_proj^T (tf32, k-permuted)
__device__ float g_part[(size_t)BHv*16*Sv];// per-(bh, coltile, row) partial sum(exp)
__device__ float g_Wscratch[(size_t)Bv*Hv*Sv*Sv];

// ==================== helpers ====================
__device__ __forceinline__ uint32_t smem_u32(const void* p) {
    uint32_t a;
    asm("{ .reg .u64 t; cvta.to.shared.u64 t, %1; cvt.u32.u64 %0, t; }"
        : "=r"(a) : "l"(p));
    return a;
}
__device__ __forceinline__ uint32_t cvt_tf32(float f) {
    uint32_t o;
    asm("cvt.rna.tf32.f32 %0, %1;" : "=r"(o) : "f"(f));
    return o;
}
__device__ __forceinline__ float tf32f(float f) {
    return __uint_as_float(cvt_tf32(f));
}
// k-permutation within 8-groups and its inverse
__device__ __forceinline__ int kperm(int c) {           // orig -> stored
    return (c < 4) ? (c * 2) : ((c - 4) * 2 + 1);
}
__device__ __forceinline__ int kinv(int p) {            // stored -> orig
    return (p & 1) ? ((p >> 1) + 4) : (p >> 1);
}
#define CP16(dst, src) \
    asm volatile("cp.async.cg.shared.global [%0], [%1], 16;" \
                 :: "r"(dst), "l"(src) : "memory")
#define CP_COMMIT() asm volatile("cp.async.commit_group;" ::: "memory")
#define CP_WAIT1()  asm volatile("cp.async.wait_group 1;" ::: "memory")
#define CP_WAIT0()  asm volatile("cp.async.wait_group 0;" ::: "memory")

#define MMA_TF32(d, a, b) \
    asm volatile("mma.sync.aligned.m16n8k8.row.col.f32.tf32.tf32.f32 " \
        "{%0,%1,%2,%3}, {%4,%5,%6,%7}, {%8,%9}, {%0,%1,%2,%3};" \
        : "+f"((d).x), "+f"((d).y), "+f"((d).z), "+f"((d).w) \
        : "r"((a)[0]), "r"((a)[1]), "r"((a)[2]), "r"((a)[3]), \
          "r"((b)[0]), "r"((b)[1]))

// ============================================================
// Zero-fill helper (R11/R13-measured): each qkv block clears 5 whole
// 128x128 strictly-upper tiles of attn_weights (streaming stores).
// ============================================================
__device__ __forceinline__ void zero_upper_chunk(float* __restrict__ wts, int id) {
    int tid = threadIdx.x;
    int trow = tid >> 5;
    int tcol = tid & 31;
    const float4 z = make_float4(0.f, 0.f, 0.f, 0.f);
#pragma unroll
    for (int tt = 0; tt < 5; tt++) {
        int tile = id * 5 + tt;
        int bh = tile / 120;
        int t = tile - bh * 120;
        int u = 119 - t;
        int m = (int)((sqrtf((float)(8 * u + 1)) - 1.0f) * 0.5f);
        while ((m + 1) * (m + 2) / 2 <= u) m++;
        while (m * (m + 1) / 2 > u) m--;
        int ry = 14 - m;
        int pref = 15 * ry - (ry * (ry - 1)) / 2;
        int cx = ry + 1 + (t - pref);
        float4* p = (float4*)(wts + ((size_t)bh * Sv + ry * 128 + trow) * Sv
                                  + cx * 128 + tcol * 4);
#pragma unroll
        for (int j = 0; j < 16; j++) {
            __stcs(p, z);
            p += 2 * Sv;
        }
    }
}

// ============================================================
// Pre-pass: round to tf32 AND k-permute within 8-groups (gather form:
// dst writes stay float4-contiguous, src reads scatter within group).
// ============================================================
__global__ void __launch_bounds__(256) round_tf32_perm(const float* __restrict__ src,
                                                       float* __restrict__ dst) {
    size_t j0 = ((size_t)blockIdx.x * 256 + threadIdx.x) * 4;
    size_t g = j0 & ~(size_t)7;
    int p0 = (int)(j0 & 7);          // 0 or 4
    float4 v;
    v.x = tf32f(src[g + kinv(p0 + 0)]);
    v.y = tf32f(src[g + kinv(p0 + 1)]);
    v.z = tf32f(src[g + kinv(p0 + 2)]);
    v.w = tf32f(src[g + kinv(p0 + 3)]);
    *(float4*)(dst + j0) = v;
}

// ============================================================
// Transpose + tf32 round + k-permute: src[R][C] -> dst[C][R'],
// R (= k dim of dst) permuted within 8-groups.
// ============================================================
__global__ void transpose_k(const float* __restrict__ src, float* __restrict__ dst,
                            int R, int C) {
    __shared__ float t[32][33];
    int bx = blockIdx.x * 32, by = blockIdx.y * 32;
    int x = bx + threadIdx.x;
#pragma unroll
    for (int i = threadIdx.y; i < 32; i += 8)
        t[i][threadIdx.x] = src[(size_t)(by + i) * C + x];
    __syncthreads();
    int x2 = by + threadIdx.x;
    int x2p = (x2 & ~7) | kperm(x2 & 7);
#pragma unroll
    for (int i = threadIdx.y; i < 32; i += 8)
        dst[(size_t)(bx + i) * R + x2p] = tf32f(t[threadIdx.x][i]);
}

// ============================================================
// Shared GEMM mainloop: 128x128 tile, K=1024, BK=32, 8 warps,
// operands k-permuted -> fragment pairs loaded as LDS.64.
// PITCH=40: conflict-free 64-bit LDS. Dynamic smem 81920 B.
// ============================================================
#define GPITCH 40
#define GABUF (128 * GPITCH)

__device__ __forceinline__ void gemm_loop_1024(const float* __restrict__ Ag,
                                               const float* __restrict__ Bg,
                                               float* sm, float4 acc[4][4]) {
    int tid = threadIdx.x, lane = tid & 31, wid = tid >> 5;
    int wm = wid >> 2, wn = wid & 3;
    int lr = lane >> 2, lc = lane & 3;

    float* As = sm;
    float* Bs = sm + 2 * GABUF;

#pragma unroll
    for (int i = 0; i < 4; i++)
#pragma unroll
        for (int j = 0; j < 4; j++) acc[i][j] = make_float4(0.f, 0.f, 0.f, 0.f);

#pragma unroll
    for (int it = 0; it < 4; it++) {
        int idx = tid + it * 256;
        int row = idx >> 3, c4 = idx & 7;
        CP16(smem_u32(As + row * GPITCH + c4 * 4), Ag + (size_t)row * KDIM + c4 * 4);
        CP16(smem_u32(Bs + row * GPITCH + c4 * 4), Bg + (size_t)row * KDIM + c4 * 4);
    }
    CP_COMMIT();

    const int NIT = KDIM / 32;
    for (int it = 0; it < NIT; it++) {
        int buf = it & 1;
        if (it + 1 < NIT) {
            int k0 = (it + 1) * 32;
            int nb = buf ^ 1;
#pragma unroll
            for (int l = 0; l < 4; l++) {
                int idx = tid + l * 256;
                int row = idx >> 3, c4 = idx & 7;
                CP16(smem_u32(As + nb * GABUF + row * GPITCH + c4 * 4),
                     Ag + (size_t)row * KDIM + k0 + c4 * 4);
                CP16(smem_u32(Bs + nb * GABUF + row * GPITCH + c4 * 4),
                     Bg + (size_t)row * KDIM + k0 + c4 * 4);
            }
            CP_COMMIT();
            CP_WAIT1();
        } else {
            CP_WAIT0();
        }
        __syncthreads();

        const float* Ab = As + buf * GABUF;
        const float* Bb = Bs + buf * GABUF;
#pragma unroll
        for (int kk = 0; kk < 32; kk += 8) {
            uint32_t af[4][4];
#pragma unroll
            for (int mt = 0; mt < 4; mt++) {
                int row = wm * 64 + mt * 16 + lr;
                float2 a01 = *(const float2*)&Ab[row * GPITCH + kk + lc * 2];
                float2 a23 = *(const float2*)&Ab[(row + 8) * GPITCH + kk + lc * 2];
                af[mt][0] = __float_as_uint(a01.x);
                af[mt][1] = __float_as_uint(a23.x);
                af[mt][2] = __float_as_uint(a01.y);
                af[mt][3] = __float_as_uint(a23.y);
            }
            uint32_t bf[4][2];
#pragma unroll
            for (int nt = 0; nt < 4; nt++) {
                int n = wn * 32 + nt * 8 + lr;
                float2 b01 = *(const float2*)&Bb[n * GPITCH + kk + lc * 2];
                bf[nt][0] = __float_as_uint(b01.x);
                bf[nt][1] = __float_as_uint(b01.y);
            }
#pragma unroll
            for (int mt = 0; mt < 4; mt++)
#pragma unroll
                for (int nt = 0; nt < 4; nt++)
                    MMA_TF32(acc[mt][nt], af[mt], bf[nt]);
        }
        __syncthreads();
    }
}

// ============================================================
// Kernel 1: QKV GEMM (mma tf32) + upper-triangle zero-fill after
// the prologue prefetch. A = g_HR (perm), B = g_WAT (perm).
// ============================================================
__global__ void __launch_bounds__(256) qkv_gemm_mma(const float* __restrict__ bias,
                                                    float* __restrict__ wts) {
    extern __shared__ float sm[];
    int m0 = blockIdx.y * 128, n0 = blockIdx.x * 128;
    int tid = threadIdx.x, lane = tid & 31, wid = tid >> 5;
    int wm = wid >> 2, wn = wid & 3;
    int lr = lane >> 2, lc = lane & 3;

    const float* Ag = g_HR + (size_t)m0 * KDIM;
    const float* Bg = g_WAT + (size_t)n0 * KDIM;

    float* As = sm;
    float* Bs = sm + 2 * GABUF;

    float4 acc[4][4];
#pragma unroll
    for (int i = 0; i < 4; i++)
#pragma unroll
        for (int j = 0; j < 4; j++) acc[i][j] = make_float4(0.f, 0.f, 0.f, 0.f);

#pragma unroll
    for (int it = 0; it < 4; it++) {
        int idx = tid + it * 256;
        int row = idx >> 3, c4 = idx & 7;
        CP16(smem_u32(As + row * GPITCH + c4 * 4), Ag + (size_t)row * KDIM + c4 * 4);
        CP16(smem_u32(Bs + row * GPITCH + c4 * 4), Bg + (size_t)row * KDIM + c4 * 4);
    }
    CP_COMMIT();

    zero_upper_chunk(wts, blockIdx.y * 24 + blockIdx.x);

    const int NIT = KDIM / 32;
    for (int it = 0; it < NIT; it++) {
        int buf = it & 1;
        if (it + 1 < NIT) {
            int k0 = (it + 1) * 32;
            int nb = buf ^ 1;
#pragma unroll
            for (int l = 0; l < 4; l++) {
                int idx = tid + l * 256;
                int row = idx >> 3, c4 = idx & 7;
                CP16(smem_u32(As + nb * GABUF + row * GPITCH + c4 * 4),
                     Ag + (size_t)row * KDIM + k0 + c4 * 4);
                CP16(smem_u32(Bs + nb * GABUF + row * GPITCH + c4 * 4),
                     Bg + (size_t)row * KDIM + k0 + c4 * 4);
            }
            CP_COMMIT();
            CP_WAIT1();
        } else {
            CP_WAIT0();
        }
        __syncthreads();

        const float* Ab = As + buf * GABUF;
        const float* Bb = Bs + buf * GABUF;
#pragma unroll
        for (int kk = 0; kk < 32; kk += 8) {
            uint32_t af[4][4];
#pragma unroll
            for (int mt = 0; mt < 4; mt++) {
                int row = wm * 64 + mt * 16 + lr;
                float2 a01 = *(const float2*)&Ab[row * GPITCH + kk + lc * 2];
                float2 a23 = *(const float2*)&Ab[(row + 8) * GPITCH + kk + lc * 2];
                af[mt][0] = __float_as_uint(a01.x);
                af[mt][1] = __float_as_uint(a23.x);
                af[mt][2] = __float_as_uint(a01.y);
                af[mt][3] = __float_as_uint(a23.y);
            }
            uint32_t bf[4][2];
#pragma unroll
            for (int nt = 0; nt < 4; nt++) {
                int n = wn * 32 + nt * 8 + lr;
                float2 b01 = *(const float2*)&Bb[n * GPITCH + kk + lc * 2];
                bf[nt][0] = __float_as_uint(b01.x);
                bf[nt][1] = __float_as_uint(b01.y);
            }
#pragma unroll
            for (int mt = 0; mt < 4; mt++)
#pragma unroll
                for (int nt = 0; nt < 4; nt++)
                    MMA_TF32(acc[mt][nt], af[mt], bf[nt]);
        }
        __syncthreads();
    }

    // epilogue: + bias, tf32-round, scatter into g_Q/g_K/g_V (UNpermuted)
#pragma unroll
    for (int mt = 0; mt < 4; mt++) {
#pragma unroll
        for (int nt = 0; nt < 4; nt++) {
            int col = n0 + wn * 32 + nt * 8 + lc * 2;
            int which = col >> 10;
            int e = col & 1023;
            int h = e >> 6, d = e & 63;
            float* dstb = (which == 0) ? g_Q : (which == 1) ? g_K : g_V;
            float b0 = bias[col], b1 = bias[col + 1];
#pragma unroll
            for (int half = 0; half < 2; half++) {
                int row = m0 + wm * 64 + mt * 16 + lr + half * 8;
                int b = row >> 11, s = row & 2047;
                float* dp = dstb + (((size_t)b * Hv + h) * Sv + s) * Dv + d;
                float v0 = (half ? acc[mt][nt].z : acc[mt][nt].x) + b0;
                float v1 = (half ? acc[mt][nt].w : acc[mt][nt].y) + b1;
                *(float2*)dp = make_float2(tf32f(v0), tf32f(v1));
            }
        }
    }
}

// ============================================================
// Kernel 4: projection (mma tf32). A = g_AO (perm), B = g_WPT (perm).
// ============================================================
__global__ void __launch_bounds__(256) proj_gemm_mma(const float* __restrict__ bias,
                                                     float* __restrict__ C) {
    extern __shared__ float sm[];
    int m0 = blockIdx.y * 128, n0 = blockIdx.x * 128;
    float4 acc[4][4];
    gemm_loop_1024(g_AO + (size_t)m0 * KDIM, g_WPT + (size_t)n0 * KDIM, sm, acc);

    int lane = threadIdx.x & 31, wid = threadIdx.x >> 5;
    int wm = wid >> 2, wn = wid & 3;
    int lr = lane >> 2, lc = lane & 3;

#pragma unroll
    for (int mt = 0; mt < 4; mt++) {
#pragma unroll
        for (int nt = 0; nt < 4; nt++) {
            int col = n0 + wn * 32 + nt * 8 + lc * 2;
            float b0 = bias[col], b1 = bias[col + 1];
#pragma unroll
            for (int half = 0; half < 2; half++) {
                int row = m0 + wm * 64 + mt * 16 + lr + half * 8;
                float v0 = (half ? acc[mt][nt].z : acc[mt][nt].x) + b0;
                float v1 = (half ? acc[mt][nt].w : acc[mt][nt].y) + b1;
                *(float2*)(C + (size_t)row * Ev + col) = make_float2(v0, v1);
            }
        }
    }
}

// ============================================================
// Kernel 2: scores (mma tf32): e = exp((Q K^T)/8), causal mask -> 0.
// (R13-measured; default-cache e stores.) Q/K unpermuted.
// ============================================================
__global__ void __launch_bounds__(256) scores_mma(float* __restrict__ Wout) {
    int bh = blockIdx.z;
    int c0 = blockIdx.x * 128;
    int r0 = blockIdx.y * 128;
    if (c0 > r0) return;   // upper tiles already zero-filled by qkv
    float* out = Wout + (size_t)bh * Sv * Sv;
    int tid = threadIdx.x;

    extern __shared__ float sm[];
    __shared__ float sred[4][128];
    const int PITCH = 68;
    float* Qs = sm;
    float* Ks = sm + 128 * PITCH;

    const float* Q = g_Q + (size_t)bh * Sv * Dv;
    const float* Kp = g_K + (size_t)bh * Sv * Dv;

#pragma unroll
    for (int it = 0; it < 8; it++) {
        int idx = tid + it * 256;
        int row = idx >> 4;
        int c4 = idx & 15;
        CP16(smem_u32(Qs + row * PITCH + c4 * 4), Q + (size_t)(r0 + row) * Dv + c4 * 4);
        CP16(smem_u32(Ks + row * PITCH + c4 * 4), Kp + (size_t)(c0 + row) * Dv + c4 * 4);
    }
    CP_COMMIT();
    CP_WAIT0();
    __syncthreads();

    int lane = tid & 31, wid = tid >> 5;
    int wm = wid >> 2, wn = wid & 3;
    int lr = lane >> 2, lc = lane & 3;

    float4 acc[4][4];
#pragma unroll
    for (int i = 0; i < 4; i++)
#pragma unroll
        for (int j = 0; j < 4; j++) acc[i][j] = make_float4(0.f, 0.f, 0.f, 0.f);

#pragma unroll
    for (int kk = 0; kk < 64; kk += 8) {
        uint32_t af[4][4];
#pragma unroll
        for (int mt = 0; mt < 4; mt++) {
            int row = wm * 64 + mt * 16 + lr;
            af[mt][0] = __float_as_uint(Qs[row * PITCH + kk + lc]);
            af[mt][1] = __float_as_uint(Qs[(row + 8) * PITCH + kk + lc]);
            af[mt][2] = __float_as_uint(Qs[row * PITCH + kk + lc + 4]);
            af[mt][3] = __float_as_uint(Qs[(row + 8) * PITCH + kk + lc + 4]);
        }
        uint32_t bf[4][2];
#pragma unroll
        for (int nt = 0; nt < 4; nt++) {
            int n = wn * 32 + nt * 8 + lr;
            bf[nt][0] = __float_as_uint(Ks[n * PITCH + kk + lc]);
            bf[nt][1] = __float_as_uint(Ks[n * PITCH + kk + lc + 4]);
        }
#pragma unroll
        for (int mt = 0; mt < 4; mt++)
#pragma unroll
            for (int nt = 0; nt < 4; nt++)
                MMA_TF32(acc[mt][nt], af[mt], bf[nt]);
    }

    const float scale = 0.125f;
#pragma unroll
    for (int mt = 0; mt < 4; mt++) {
#pragma unroll
        for (int half = 0; half < 2; half++) {
            int r = r0 + wm * 64 + mt * 16 + lr + half * 8;
            float rsum = 0.f;
#pragma unroll
            for (int nt = 0; nt < 4; nt++) {
                int col = c0 + wn * 32 + nt * 8 + lc * 2;
                float v0 = (half ? acc[mt][nt].z : acc[mt][nt].x) * scale;
                float v1 = (half ? acc[mt][nt].w : acc[mt][nt].y) * scale;
                float e0 = (col <= r) ? __expf(v0) : 0.f;
                float e1 = (col + 1 <= r) ? __expf(v1) : 0.f;
                *(float2*)(out + (size_t)r * Sv + col) = make_float2(e0, e1);
                rsum += e0 + e1;
            }
            rsum += __shfl_xor_sync(0xffffffffu, rsum, 1);
            rsum += __shfl_xor_sync(0xffffffffu, rsum, 2);
            if (lc == 0)
                sred[wn][wm * 64 + mt * 16 + half * 8 + lr] = rsum;
        }
    }
    __syncthreads();
    if (tid < 128) {
        float p = sred[0][tid] + sred[1][tid] + sred[2][tid] + sred[3][tid];
        g_part[((size_t)bh * 16 + (c0 >> 7)) * Sv + r0 + tid] = p;
    }
}

// ============================================================
// Kernel 3: fused normalize + PV (mma tf32), cp.async double-buffered.
// (R13-measured.) Epilogue writes g_AO with k-permutation for proj.
// ============================================================
__global__ void __launch_bounds__(256) pv_fused2(float* __restrict__ Wts) {
    int bh = blockIdx.y;
    int rt = (gridDim.x - 1) - blockIdx.x;   // heavy row-tiles first
    int r0 = rt * 128;
    float* P = Wts + (size_t)bh * Sv * Sv;
    const float* V = g_V + (size_t)bh * Sv * Dv;

    extern __shared__ float sm[];
    const int PP = 36, VP = 72;
    const int PBUF = 128 * PP;
    const int VBUF = 32 * VP;
    float* Ps = sm;
    float* Vs = sm + 2 * PBUF;
    __shared__ float rinv[128];

    int tid = threadIdx.x, lane = tid & 31, wid = tid >> 5;
    int wm = wid >> 1, wn = wid & 1;
    int lr = lane >> 2, lc = lane & 3;

    if (tid < 128) {
        float s = 0.f;
        const float* pp = g_part + (size_t)bh * 16 * Sv + r0 + tid;
        for (int ct = 0; ct <= rt; ct++) s += pp[(size_t)ct * Sv];
        rinv[tid] = 1.0f / s;
    }

    float4 acc[2][4];
#pragma unroll
    for (int i = 0; i < 2; i++)
#pragma unroll
        for (int j = 0; j < 4; j++) acc[i][j] = make_float4(0.f, 0.f, 0.f, 0.f);

    int kend = r0 + 128;
    int nit = kend >> 5;

    // prologue: stage 0
    {
#pragma unroll
        for (int it = 0; it < 4; it++) {
            int idx = tid + it * 256;
            int row = idx >> 3, c4 = idx & 7;
            CP16(smem_u32(Ps + row * PP + c4 * 4),
                 P + (size_t)(r0 + row) * Sv + c4 * 4);
        }
#pragma unroll
        for (int it = 0; it < 2; it++) {
            int idx = tid + it * 256;
            int row = idx >> 4, c4 = idx & 15;
            CP16(smem_u32(Vs + row * VP + c4 * 4),
                 V + (size_t)row * Dv + c4 * 4);
        }
        CP_COMMIT();
    }

    __syncthreads();
    float ri[2][2];
#pragma unroll
    for (int mt = 0; mt < 2; mt++) {
        ri[mt][0] = rinv[wm * 32 + mt * 16 + lr];
        ri[mt][1] = rinv[wm * 32 + mt * 16 + lr + 8];
    }
    float riw[4];
#pragma unroll
    for (int it = 0; it < 4; it++) riw[it] = rinv[(tid >> 3) + it * 32];

    for (int itk = 0; itk < nit; itk++) {
        int buf = itk & 1;
        int kc = itk * 32;
        if (itk + 1 < nit) {
            int kn = (itk + 1) * 32;
            int nb = buf ^ 1;
#pragma unroll
            for (int it = 0; it < 4; it++) {
                int idx = tid + it * 256;
                int row = idx >> 3, c4 = idx & 7;
                CP16(smem_u32(Ps + nb * PBUF + row * PP + c4 * 4),
                     P + (size_t)(r0 + row) * Sv + kn + c4 * 4);
            }
#pragma unroll
            for (int it = 0; it < 2; it++) {
                int idx = tid + it * 256;
                int row = idx >> 4, c4 = idx & 15;
                CP16(smem_u32(Vs + nb * VBUF + row * VP + c4 * 4),
                     V + (size_t)(kn + row) * Dv + c4 * 4);
            }
            CP_COMMIT();
            CP_WAIT1();
        } else {
            CP_WAIT0();
        }
        __syncthreads();

        const float* Pb = Ps + buf * PBUF;
        const float* Vb = Vs + buf * VBUF;

        // stream final attn_weights w = e * rinv back to gmem
#pragma unroll
        for (int it = 0; it < 4; it++) {
            int idx = tid + it * 256;
            int row = idx >> 3, c4 = idx & 7;
            float4 ev = *(const float4*)(Pb + row * PP + c4 * 4);
            float inv = riw[it];
            ev.x *= inv; ev.y *= inv; ev.z *= inv; ev.w *= inv;
            *(float4*)(P + (size_t)(r0 + row) * Sv + kc + c4 * 4) = ev;
        }

#pragma unroll
        for (int kk = 0; kk < 32; kk += 8) {
            uint32_t af[2][4];
#pragma unroll
            for (int mt = 0; mt < 2; mt++) {
                int row = wm * 32 + mt * 16 + lr;
                af[mt][0] = cvt_tf32(Pb[row * PP + kk + lc] * ri[mt][0]);
                af[mt][1] = cvt_tf32(Pb[(row + 8) * PP + kk + lc] * ri[mt][1]);
                af[mt][2] = cvt_tf32(Pb[row * PP + kk + lc + 4] * ri[mt][0]);
                af[mt][3] = cvt_tf32(Pb[(row + 8) * PP + kk + lc + 4] * ri[mt][1]);
            }
            uint32_t bf[4][2];
#pragma unroll
            for (int nt = 0; nt < 4; nt++) {
                int n = wn * 32 + nt * 8 + lr;
                bf[nt][0] = __float_as_uint(Vb[(kk + lc) * VP + n]);
                bf[nt][1] = __float_as_uint(Vb[(kk + 4 + lc) * VP + n]);
            }
#pragma unroll
            for (int mt = 0; mt < 2; mt++)
#pragma unroll
                for (int nt = 0; nt < 4; nt++)
                    MMA_TF32(acc[mt][nt], af[mt], bf[nt]);
        }
        __syncthreads();
    }

    // epilogue: write g_AO with K-PERMUTED columns (proj consumes it)
    int b = bh >> 4, h = bh & 15;
#pragma unroll
    for (int mt = 0; mt < 2; mt++) {
#pragma unroll
        for (int nt = 0; nt < 4; nt++) {
            int d = wn * 32 + nt * 8 + lc * 2;
            int q = d & 7;                       // even
            int p0 = kperm(q);                   // stored pos of d
            int base = h * Dv + (d & ~7);
#pragma unroll
            for (int half = 0; half < 2; half++) {
                int r = r0 + wm * 32 + mt * 16 + lr + half * 8;
                float v0 = half ? acc[mt][nt].z : acc[mt][nt].x;
                float v1 = half ? acc[mt][nt].w : acc[mt][nt].y;
                float* dp = g_AO + ((size_t)(b * Sv + r)) * Ev + base;
                dp[p0] = tf32f(v0);
                dp[p0 + 2] = tf32f(v1);          // kperm(q+1) = kperm(q)+2
            }
        }
    }
}

// ============================================================
// Launch
// ============================================================
extern "C" void kernel_launch(void* const* d_in, const int* in_sizes, int n_in,
                              void* d_out, int out_size) {
    const float* hs     = (const float*)d_in[0];
    const float* w_attn = (const float*)d_in[1];
    const float* b_attn = (const float*)d_in[2];
    const float* w_proj = (const float*)d_in[3];
    const float* b_proj = (const float*)d_in[4];
    float* out = (float*)d_out;

    const size_t AO_N = (size_t)Bv * Sv * Ev;
    const size_t W_N  = (size_t)Bv * Hv * Sv * Sv;

    float* wts;
    if ((size_t)out_size >= AO_N + W_N) {
        wts = out + AO_N;
    } else {
        void* p = nullptr;
        cudaGetSymbolAddress(&p, g_Wscratch);
        wts = (float*)p;
    }

    float* hr;  { void* p = nullptr; cudaGetSymbolAddress(&p, g_HR);  hr  = (float*)p; }
    float* wat; { void* p = nullptr; cudaGetSymbolAddress(&p, g_WAT); wat = (float*)p; }
    float* wpt; { void* p = nullptr; cudaGetSymbolAddress(&p, g_WPT); wpt = (float*)p; }

    const int GEMM_SMEM = 2 * 2 * 128 * GPITCH * 4;        // 81920
    const int SCORES_SMEM = 2 * 128 * 68 * 4;              // 69632
    const int PV_SMEM = (2 * 128 * 36 + 2 * 32 * 72) * 4;  // 55296
    cudaFuncSetAttribute(qkv_gemm_mma,
                         cudaFuncAttributeMaxDynamicSharedMemorySize, GEMM_SMEM);
    cudaFuncSetAttribute(proj_gemm_mma,
                         cudaFuncAttributeMaxDynamicSharedMemorySize, GEMM_SMEM);
    cudaFuncSetAttribute(scores_mma,
                         cudaFuncAttributeMaxDynamicSharedMemorySize, SCORES_SMEM);
    cudaFuncSetAttribute(pv_fused2,
                         cudaFuncAttributeMaxDynamicSharedMemorySize, PV_SMEM);

    round_tf32_perm<<<(Bv * Sv * Ev) / (256 * 4), 256>>>(hs, hr);
    transpose_k<<<dim3(N3 / 32, Ev / 32), dim3(32, 8)>>>(w_attn, wat, Ev, N3);
    transpose_k<<<dim3(Ev / 32, Ev / 32), dim3(32, 8)>>>(w_proj, wpt, Ev, Ev);

    qkv_gemm_mma<<<dim3(N3 / 128, (Bv * Sv) / 128), 256, GEMM_SMEM>>>(b_attn, wts);
    scores_mma<<<dim3(Sv / 128, Sv / 128, BHv), 256, SCORES_SMEM>>>(wts);
    pv_fused2<<<dim3(Sv / 128, BHv), 256, PV_SMEM>>>(wts);
    proj_gemm_mma<<<dim3(Ev / 128, (Bv * Sv) / 128), 256, GEMM_SMEM>>>(b_proj, out);
}